// round 7
// baseline (speedup 1.0000x reference)
#include <cuda_runtime.h>
typedef unsigned long long u64;

#define Bn 16
#define Cn 32
#define Sn 256
#define Mn 12
#define Rn 24
#define Ln 4
#define BCn (Bn*Cn)
#define WTN (Ln*Rn*Mn*Cn*Cn)
#define SS (Sn*Sn)

__device__ float g_h[(size_t)BCn*SS];
__device__ float g_Yq[(size_t)Bn*Rn*Cn*Sn];   // [b][q][c][y]
__device__ u64   g_T2[(size_t)Bn*Sn*Cn*Mn];   // [b][y][o][k] {tr,ti}
__device__ float g_Wtr[WTN];
__device__ float g_Wti[WTN];
__device__ u64   g_tcF[Rn*Sn];
__device__ u64   g_tsF[Rn*Sn];
__device__ float g_trigH[Rn*128];             // q<12: cos(q w), q>=12: sin((q-12) w)
__device__ u64   g_dpk[22*128];

__device__ __forceinline__ u64 pk2(float x, float y) {
    u64 r; asm("mov.b64 %0,{%1,%2};" : "=l"(r) : "f"(x), "f"(y)); return r;
}
__device__ __forceinline__ void up2(u64 a, float& x, float& y) {
    asm("mov.b64 {%0,%1},%2;" : "=f"(x), "=f"(y) : "l"(a));
}
__device__ __forceinline__ u64 f2fma(u64 a, u64 b, u64 c) {
    u64 d; asm("fma.rn.f32x2 %0,%1,%2,%3;" : "=l"(d) : "l"(a), "l"(b), "l"(c)); return d;
}

__global__ void k_setup() {
    int q = blockIdx.x, w = threadIdx.x;
    int ky = (q < Mn) ? q : 232 + q;
    float s, c;
    sincospif((float)((ky*w) & 255) * (2.0f/256.0f), &s, &c);
    g_tcF[q*Sn + w] = pk2(c, c);
    g_tsF[q*Sn + w] = pk2(s, s);
    if (w < 128) {
        int kk = (q < Mn) ? q : q - Mn;
        float s2, c2;
        sincospif((float)((kk*w) & 255) * (2.0f/256.0f), &s2, &c2);
        g_trigH[q*128 + w] = (q < Mn) ? c2 : s2;
        if (q >= 1 && q < Mn) {
            float sg = (q & 1) ? -1.f : 1.f;
            g_dpk[(q-1)*128 + w]  = pk2(c2, sg*c2);
            g_dpk[(10+q)*128 + w] = pk2(s2, sg*s2);
        }
    }
}

__global__ void k_wt(const float* __restrict__ w1r, const float* __restrict__ w1i,
                     const float* __restrict__ w2r, const float* __restrict__ w2i) {
    int flat = blockIdx.x*256 + threadIdx.x;
    if (flat >= WTN) return;
    int o = flat & 31;
    int i = (flat >> 5) & 31;
    int k = (flat >> 10) % Mn;
    int r = (flat / (Mn*Cn*Cn)) % Rn;
    int l =  flat / (Rn*Mn*Cn*Cn);
    int ky = (r < Mn) ? r : r - Mn;
    size_t s = ((((size_t)l*Cn + i)*Cn + o)*Mn + ky)*Mn + k;
    const float sc = 1.0f/65536.0f;
    if (r < Mn) { g_Wtr[flat] = w1r[s]*sc; g_Wti[flat] = w1i[s]*sc; }
    else        { g_Wtr[flat] = w2r[s]*sc; g_Wti[flat] = w2i[s]*sc; }
}

// ---- k_modes: byte-identical to round-5 (measured 71us, correct) ----
__global__ void __launch_bounds__(768) k_modes(int l) {
    extern __shared__ u64 smu[];
    u64* sY = smu;
    u64* sZ = smu + 256*33;
    u64* sO = sZ + 32*25;
    int b = blockIdx.x / Mn, k = blockIdx.x % Mn;
    int t = threadIdx.x;
    const float* yre = g_Yq + (size_t)((b*Rn + k)*Cn)*Sn;
    const float* yim = g_Yq + (size_t)((b*Rn + Mn + k)*Cn)*Sn;
    for (int idx = t; idx < Cn*Sn; idx += 768) {
        int c = idx >> 8, y = idx & 255;
        sY[y*33 + c] = pk2(yre[idx], yim[idx]);
    }
    __syncthreads();
    int r = t >> 5, lane = t & 31;
    {
        u64 pm = (r & 1) ? pk2(-1.f, -1.f) : pk2(1.f, 1.f);
        const u64* tc = g_tcF + r*Sn;
        const u64* ts = g_tsF + r*Sn;
        u64 accP = 0, accQ = 0;
        #pragma unroll 4
        for (int hp = 0; hp < 128; hp++) {
            u64 ya = sY[hp*33 + lane];
            u64 yb = sY[(hp+128)*33 + lane];
            u64 u = f2fma(yb, pm, ya);
            accP = f2fma(u, __ldg(tc + hp), accP);
            accQ = f2fma(u, __ldg(ts + hp), accQ);
        }
        float px, py, qx, qy; up2(accP, px, py); up2(accQ, qx, qy);
        sZ[lane*25 + r] = pk2(px + qy, py - qx);
    }
    __syncthreads();
    {
        size_t wb = ((size_t)((l*Rn + r)*Mn + k))*(Cn*Cn) + lane;
        float orr = 0.f, oii = 0.f;
        #pragma unroll 8
        for (int i = 0; i < Cn; i++) {
            float zr, zi; up2(sZ[i*25 + r], zr, zi);
            float ar = __ldg(g_Wtr + wb + (size_t)i*Cn);
            float ai = __ldg(g_Wti + wb + (size_t)i*Cn);
            orr += zr*ar - zi*ai;
            oii += zr*ai + zi*ar;
        }
        sO[lane*25 + r] = pk2(orr, oii);
    }
    __syncthreads();
    {
        int h = t & 255, third = t >> 8;
        int o0 = third*11;
        int on = (third == 2) ? 10 : 11;
        u64 accP[11], accQ[11];
        #pragma unroll
        for (int i = 0; i < 11; i++) { accP[i] = 0; accQ[i] = 0; }
        for (int rr = 0; rr < Rn; rr++) {
            u64 c2 = __ldg(g_tcF + rr*Sn + h);
            u64 s2 = __ldg(g_tsF + rr*Sn + h);
            #pragma unroll
            for (int i = 0; i < 11; i++) {
                u64 O = sO[(o0 + i)*25 + rr];
                accP[i] = f2fma(O, c2, accP[i]);
                accQ[i] = f2fma(O, s2, accQ[i]);
            }
        }
        u64* Tb = g_T2 + ((size_t)(b*Sn + h)*Cn)*Mn + k;
        #pragma unroll
        for (int i = 0; i < 11; i++) if (i < on) {
            float px, py, qx, qy; up2(accP[i], px, py); up2(accQ[i], qx, qy);
            Tb[(size_t)(o0 + i)*Mn] = pk2(px - qy, qx + py);
        }
    }
}

// ---- k_layer: 512 thr = 128 pixel-pairs x 4 output-groups of 8 ----
template<int MODE>
__global__ void __launch_bounds__(512, 2) k_layer(
    const float* __restrict__ x,
    const float* __restrict__ pw, const float* __restrict__ pb,
    const float* __restrict__ wsw, const float* __restrict__ wsb,
    const float* __restrict__ qw, const float* __restrict__ qb,
    int l, float* __restrict__ out)
{
    extern __shared__ u64 smu[];
    u64* sW   = smu;                     // [55][34] {W,W}
    u64* sD   = smu + 55*34;             // [32][129]
    u64* sRed = sD + 32*129;             // [4][128]
    float* sTrig = (float*)(sRed + 4*128); // [24][132]
    float* sQ = sTrig + 24*132;          // [32]

    int t = threadIdx.x, w = t & 127, g = t >> 7;   // g in 0..3
    int b = blockIdx.x >> 8, y = blockIdx.x & 255;

    for (int i = t; i < Rn*128; i += 512)
        sTrig[(i >> 7)*132 + (i & 127)] = g_trigH[i];

    if (MODE >= 1) {
        const u64* T2 = g_T2 + (size_t)blockIdx.x * (Cn*Mn);
        for (int idx = t; idx < 55*Cn; idx += 512) {
            int j = idx >> 5, o = idx & 31;
            float W, tr, ti;
            if (j < 32) W = wsw[l*Cn*Cn + o*Cn + j];
            else if (j == 32) { up2(T2[o*Mn], tr, ti); W = wsb[l*Cn + o] + tr; }
            else if (j < 44)  { up2(T2[o*Mn + (j-32)], tr, ti); W =  2.f*tr; }
            else              { up2(T2[o*Mn + (j-43)], tr, ti); W = -2.f*ti; }
            sW[j*34 + o] = pk2(W, W);
        }
        if (MODE == 2 && t < Cn) sQ[t] = qw[t];
        for (int idx = t; idx < Cn*128; idx += 512) {
            int c = idx >> 7, ww = idx & 127;
            const float* hp = g_h + (size_t)(b*Cn + c)*SS + (size_t)y*Sn + ww;
            sD[c*129 + ww] = pk2(hp[0], hp[128]);
        }
    }
    __syncthreads();

    if (MODE == 0) {
        float xx = x[(size_t)blockIdx.x*Sn + w];
        float xy = x[(size_t)blockIdx.x*Sn + w + 128];
        float gy  = -1.f + (2.f/255.f)*(float)y;
        float gxx = -1.f + (2.f/255.f)*(float)w;
        float gxy = -1.f + (2.f/255.f)*(float)(w + 128);
        #pragma unroll
        for (int cc = 0; cc < 8; cc++) {
            int c = g*8 + cc;
            float w0 = pw[c*3], w1 = pw[c*3+1], w2 = pw[c*3+2], bb = pb[c];
            float vx = w0*xx + w1*gy + w2*gxx + bb;
            float vy = w0*xy + w1*gy + w2*gxy + bb;
            float* hp = g_h + (size_t)(b*Cn + c)*SS + (size_t)y*Sn + w;
            hp[0] = vx; hp[128] = vy;
            sD[c*129 + w] = pk2(vx + vy, vx - vy);
        }
    } else {
        u64 acc[8];
        #pragma unroll
        for (int i = 0; i < 8; i++) acc[i] = 0ull;
        #pragma unroll 4
        for (int j = 0; j < 32; j++) {
            u64 d = sD[j*129 + w];
            const ulonglong2* wp = (const ulonglong2*)(sW + j*34 + g*8);
            #pragma unroll
            for (int o2 = 0; o2 < 4; o2++) {
                ulonglong2 q2 = wp[o2];
                acc[2*o2]   = f2fma(d, q2.x, acc[2*o2]);
                acc[2*o2+1] = f2fma(d, q2.y, acc[2*o2+1]);
            }
        }
        {
            u64 ONE = pk2(1.f, 1.f);
            const ulonglong2* wp = (const ulonglong2*)(sW + 32*34 + g*8);
            #pragma unroll
            for (int o2 = 0; o2 < 4; o2++) {
                ulonglong2 q2 = wp[o2];
                acc[2*o2]   = f2fma(ONE, q2.x, acc[2*o2]);
                acc[2*o2+1] = f2fma(ONE, q2.y, acc[2*o2+1]);
            }
        }
        #pragma unroll 2
        for (int j = 33; j < 55; j++) {
            u64 d = __ldg(g_dpk + (j-33)*128 + w);
            const ulonglong2* wp = (const ulonglong2*)(sW + j*34 + g*8);
            #pragma unroll
            for (int o2 = 0; o2 < 4; o2++) {
                ulonglong2 q2 = wp[o2];
                acc[2*o2]   = f2fma(d, q2.x, acc[2*o2]);
                acc[2*o2+1] = f2fma(d, q2.y, acc[2*o2+1]);
            }
        }
        __syncthreads();
        if (MODE == 1) {
            #pragma unroll
            for (int oo = 0; oo < 8; oo++) {
                int o = g*8 + oo;
                float vx, vy; up2(acc[oo], vx, vy);
                vx = fmaxf(vx, 0.f); vy = fmaxf(vy, 0.f);
                float* hp = g_h + (size_t)(b*Cn + o)*SS + (size_t)y*Sn + w;
                hp[0] = vx; hp[128] = vy;
                sD[o*129 + w] = pk2(vx + vy, vx - vy);
            }
        } else {
            float px = 0.f, py = 0.f;
            #pragma unroll
            for (int oo = 0; oo < 8; oo++) {
                float vx, vy; up2(acc[oo], vx, vy);
                float q = sQ[g*8 + oo];
                px += q*vx; py += q*vy;
            }
            sRed[g*128 + w] = pk2(px, py);
            __syncthreads();
            if (g == 0) {
                float sx = px, sy = py;
                #pragma unroll
                for (int gg = 1; gg < 4; gg++) {
                    float rx, ry; up2(sRed[gg*128 + w], rx, ry);
                    sx += rx; sy += ry;
                }
                float q0 = qb[0];
                out[(size_t)blockIdx.x*Sn + w]       = sx + q0;
                out[(size_t)blockIdx.x*Sn + w + 128] = sy + q0;
            }
            return;
        }
    }
    __syncthreads();

    // folded row-DFT: thread = (o = t>>4, u = t&15); u<12 handles cos_u and sin_u
    int o = t >> 4, u = t & 15;
    if (u < Mn) {
        const u64* vp = sD + o*129;
        const float* tc = sTrig + u*132;          // cos(u w)
        const float* tsn = sTrig + (Mn + u)*132;  // sin(u w)
        bool p = (u & 1);
        float ac = 0.f, as = 0.f;
        #pragma unroll 4
        for (int ww = 0; ww < 128; ww++) {
            float e, dd; up2(vp[ww], e, dd);
            float src = p ? dd : e;
            ac += src*tc[ww];
            as += src*tsn[ww];
        }
        size_t yc = ((size_t)(b*Rn + u)*Cn + o)*Sn + y;
        g_Yq[yc]                    =  ac;   // re(k=u)
        g_Yq[yc + (size_t)Mn*Cn*Sn] = -as;   // im(k=u)
    }
}

#define SMEM_LAYER ((55*34 + 32*129 + 4*128)*8 + (24*132)*4 + 32*4)
#define SMEM_MODES ((256*33 + 32*25 + 33*25)*8)

extern "C" void kernel_launch(void* const* d_in, const int* in_sizes, int n_in,
                              void* d_out, int out_size) {
    (void)in_sizes; (void)n_in; (void)out_size;
    const float* x    = (const float*)d_in[0];
    const float* p_w  = (const float*)d_in[1];
    const float* p_b  = (const float*)d_in[2];
    const float* ws_w = (const float*)d_in[3];
    const float* ws_b = (const float*)d_in[4];
    const float* w1r  = (const float*)d_in[5];
    const float* w1i  = (const float*)d_in[6];
    const float* w2r  = (const float*)d_in[7];
    const float* w2i  = (const float*)d_in[8];
    const float* q_w  = (const float*)d_in[9];
    const float* q_b  = (const float*)d_in[10];
    float* out = (float*)d_out;

    cudaFuncSetAttribute(k_layer<0>, cudaFuncAttributeMaxDynamicSharedMemorySize, SMEM_LAYER);
    cudaFuncSetAttribute(k_layer<1>, cudaFuncAttributeMaxDynamicSharedMemorySize, SMEM_LAYER);
    cudaFuncSetAttribute(k_layer<2>, cudaFuncAttributeMaxDynamicSharedMemorySize, SMEM_LAYER);
    cudaFuncSetAttribute(k_modes,    cudaFuncAttributeMaxDynamicSharedMemorySize, SMEM_MODES);

    k_setup<<<Rn, Sn>>>();
    k_wt<<<(WTN + 255)/256, 256>>>(w1r, w1i, w2r, w2i);
    k_layer<0><<<Bn*Sn, 512, SMEM_LAYER>>>(x, p_w, p_b, nullptr, nullptr, nullptr, nullptr, 0, out);
    for (int l = 0; l < Ln; l++) {
        k_modes<<<Bn*Mn, 768, SMEM_MODES>>>(l);
        if (l < Ln - 1)
            k_layer<1><<<Bn*Sn, 512, SMEM_LAYER>>>(nullptr, nullptr, nullptr,
                                                   ws_w, ws_b, q_w, q_b, l, out);
        else
            k_layer<2><<<Bn*Sn, 512, SMEM_LAYER>>>(nullptr, nullptr, nullptr,
                                                   ws_w, ws_b, q_w, q_b, l, out);
    }
}

// round 8
// speedup vs baseline: 1.1292x; 1.1292x over previous
#include <cuda_runtime.h>
typedef unsigned long long u64;

#define Bn 16
#define Cn 32
#define Sn 256
#define Mn 12
#define Rn 24
#define Ln 4
#define BCn (Bn*Cn)
#define WTN (Ln*Rn*Mn*Cn*Cn)
#define SS (Sn*Sn)

__device__ float g_h[(size_t)BCn*SS];
__device__ float g_Y[(size_t)Bn*Sn*Rn*Cn];    // [b][y][q][c], q<12 re, q>=12 im
__device__ u64   g_T2[(size_t)Bn*Sn*Cn*Mn];   // [b][y][o][k] {tr,ti}
__device__ float g_Wtr[WTN];
__device__ float g_Wti[WTN];
__device__ float g_trig[Rn*Sn];               // rows 0-11 cos(k w th), 12-23 sin
__device__ u64   g_tcF[Rn*Sn];                // {c,c} at ky(r)*h
__device__ u64   g_tsF[Rn*Sn];

__device__ __forceinline__ u64 pk2(float x, float y) {
    u64 r; asm("mov.b64 %0,{%1,%2};" : "=l"(r) : "f"(x), "f"(y)); return r;
}
__device__ __forceinline__ void up2(u64 a, float& x, float& y) {
    asm("mov.b64 {%0,%1},%2;" : "=f"(x), "=f"(y) : "l"(a));
}
__device__ __forceinline__ u64 f2fma(u64 a, u64 b, u64 c) {
    u64 d; asm("fma.rn.f32x2 %0,%1,%2,%3;" : "=l"(d) : "l"(a), "l"(b), "l"(c)); return d;
}

__global__ void k_setupA() {   // launch 0
    int q = blockIdx.x, w = threadIdx.x;
    int kq = (q < Mn) ? q : q - Mn;
    float s, c;
    sincospif((float)((kq*w) & 255) * (2.0f/256.0f), &s, &c);
    g_trig[q*Sn + w] = (q < Mn) ? c : s;
}
__global__ void k_setupB() {   // launch 1
    int q = blockIdx.x, w = threadIdx.x;
    int ky = (q < Mn) ? q : 232 + q;
    float s, c;
    sincospif((float)((ky*w) & 255) * (2.0f/256.0f), &s, &c);
    g_tcF[q*Sn + w] = pk2(c, c);
    g_tsF[q*Sn + w] = pk2(s, s);
}

__global__ void k_wt(const float* __restrict__ w1r, const float* __restrict__ w1i,
                     const float* __restrict__ w2r, const float* __restrict__ w2i) {
    int flat = blockIdx.x*256 + threadIdx.x;   // launch 2
    if (flat >= WTN) return;
    int o = flat & 31;
    int i = (flat >> 5) & 31;
    int k = (flat >> 10) % Mn;
    int r = (flat / (Mn*Cn*Cn)) % Rn;
    int l =  flat / (Rn*Mn*Cn*Cn);
    int ky = (r < Mn) ? r : r - Mn;
    size_t s = ((((size_t)l*Cn + i)*Cn + o)*Mn + ky)*Mn + k;
    const float sc = 1.0f/65536.0f;
    if (r < Mn) { g_Wtr[flat] = w1r[s]*sc; g_Wti[flat] = w1i[s]*sc; }
    else        { g_Wtr[flat] = w2r[s]*sc; g_Wti[flat] = w2i[s]*sc; }
}

// ---- k_modes: r5 core (measured 71us), Y reads adapted to [b][y][q][c] ----
__global__ void __launch_bounds__(768) k_modes(int l) {
    extern __shared__ u64 smu[];
    u64* sY = smu;              // [256][33] {re,im}
    u64* sZ = smu + 256*33;     // [c][25]
    u64* sO = sZ + 32*25;       // [o][25] padded to 33 rows
    int b = blockIdx.x / Mn, k = blockIdx.x % Mn;
    int t = threadIdx.x;
    const float* yb = g_Y + (size_t)b*Sn*Rn*Cn;
    for (int idx = t; idx < Cn*Sn; idx += 768) {
        int y = idx >> 5, c = idx & 31;
        const float* yp = yb + (size_t)y*(Rn*Cn) + k*Cn + c;
        sY[y*33 + c] = pk2(yp[0], yp[Mn*Cn]);
    }
    __syncthreads();
    int r = t >> 5, lane = t & 31;
    {
        u64 pm = (r & 1) ? pk2(-1.f, -1.f) : pk2(1.f, 1.f);
        const u64* tc = g_tcF + r*Sn;
        const u64* ts = g_tsF + r*Sn;
        u64 accP = 0, accQ = 0;
        #pragma unroll 4
        for (int hp = 0; hp < 128; hp++) {
            u64 ya = sY[hp*33 + lane];
            u64 yc = sY[(hp+128)*33 + lane];
            u64 u = f2fma(yc, pm, ya);
            accP = f2fma(u, __ldg(tc + hp), accP);
            accQ = f2fma(u, __ldg(ts + hp), accQ);
        }
        float px, py, qx, qy; up2(accP, px, py); up2(accQ, qx, qy);
        sZ[lane*25 + r] = pk2(px + qy, py - qx);
    }
    __syncthreads();
    {
        size_t wb = ((size_t)((l*Rn + r)*Mn + k))*(Cn*Cn) + lane;
        float orr = 0.f, oii = 0.f;
        #pragma unroll 8
        for (int i = 0; i < Cn; i++) {
            float zr, zi; up2(sZ[i*25 + r], zr, zi);
            float ar = __ldg(g_Wtr + wb + (size_t)i*Cn);
            float ai = __ldg(g_Wti + wb + (size_t)i*Cn);
            orr += zr*ar - zi*ai;
            oii += zr*ai + zi*ar;
        }
        sO[lane*25 + r] = pk2(orr, oii);
    }
    __syncthreads();
    {
        int h = t & 255, third = t >> 8;
        int o0 = third*11;
        int on = (third == 2) ? 10 : 11;
        u64 accP[11], accQ[11];
        #pragma unroll
        for (int i = 0; i < 11; i++) { accP[i] = 0; accQ[i] = 0; }
        for (int rr = 0; rr < Rn; rr++) {
            u64 c2 = __ldg(g_tcF + rr*Sn + h);
            u64 s2 = __ldg(g_tsF + rr*Sn + h);
            #pragma unroll
            for (int i = 0; i < 11; i++) {
                u64 O = sO[(o0 + i)*25 + rr];
                accP[i] = f2fma(O, c2, accP[i]);
                accQ[i] = f2fma(O, s2, accQ[i]);
            }
        }
        u64* Tb = g_T2 + ((size_t)(b*Sn + h)*Cn)*Mn + k;
        #pragma unroll
        for (int i = 0; i < 11; i++) if (i < on) {
            float px, py, qx, qy; up2(accP[i], px, py); up2(accQ[i], qx, qy);
            Tb[(size_t)(o0 + i)*Mn] = pk2(px - qy, qx + py);
        }
    }
}

// ---- k_layer: round-2 structure (measured best) + hoisted LDG + coalesced Y ----
template<int MODE>
__global__ void __launch_bounds__(256) k_layer(
    const float* __restrict__ x,
    const float* __restrict__ pw, const float* __restrict__ pb,
    const float* __restrict__ wsw, const float* __restrict__ wsb,
    const float* __restrict__ qw, const float* __restrict__ qb,
    int l, float* __restrict__ out)
{
    extern __shared__ float sm[];
    float* s_v    = sm;                      // [32][260]
    float* s_trig = sm + Cn*260;             // [24][260]
    float* s_t12  = sm + (Cn + Rn)*260;      // [32][24]
    float* s_ws   = s_t12 + Cn*(2*Mn);       // [32][32]
    float* s_wb   = s_ws + Cn*Cn;
    float* s_qw   = s_wb + Cn;

    int t = threadIdx.x;
    int b = blockIdx.x >> 8, y = blockIdx.x & 255;
    int w = t;
    float* hrow = g_h + (((size_t)b*Cn)*Sn + y)*Sn + w;

    // hoist gmem latency above staging
    float hin[Cn];
    if (MODE >= 1) {
        #pragma unroll
        for (int i = 0; i < Cn; i++) hin[i] = hrow[(size_t)i*SS];
    }

    for (int i = t; i < Rn*Sn; i += 256)
        s_trig[(i >> 8)*260 + (i & 255)] = g_trig[i];
    if (MODE >= 1) {
        const u64* T2 = g_T2 + (size_t)blockIdx.x * (Cn*Mn);
        for (int i = t; i < Cn*Mn; i += 256) {
            int o = i / Mn, k = i % Mn;
            float tr, ti; up2(T2[i], tr, ti);
            s_t12[o*24 + k]      = tr;
            s_t12[o*24 + Mn + k] = ti;
        }
        for (int i = t; i < Cn*Cn; i += 256) s_ws[i] = wsw[l*Cn*Cn + i];
        if (t < Cn) { s_wb[t] = wsb[l*Cn + t]; s_qw[t] = qw[t]; }
    }
    __syncthreads();

    if (MODE == 0) {
        float xin = x[(size_t)blockIdx.x*Sn + w];
        float gy = -1.f + (2.f/255.f)*(float)y;
        float gx = -1.f + (2.f/255.f)*(float)w;
        #pragma unroll 8
        for (int c = 0; c < Cn; c++) {
            float v = pw[c*3+0]*xin + pw[c*3+1]*gy + pw[c*3+2]*gx + pb[c];
            hrow[(size_t)c*SS] = v;
            s_v[c*260 + w] = v;
        }
    } else {
        float cww[Mn], sww[Mn];
        #pragma unroll
        for (int k = 0; k < Mn; k++) {
            cww[k] = s_trig[k*260 + w];
            sww[k] = s_trig[(Mn + k)*260 + w];
        }
        float proj = 0.f;
        #pragma unroll 2
        for (int o = 0; o < Cn; o++) {
            const float* wsp = s_ws + o*Cn;
            float acc = s_wb[o];
            #pragma unroll
            for (int i = 0; i < Cn; i++) acc += wsp[i]*hin[i];
            const float* tp = s_t12 + o*24;
            float four = tp[0];                       // DC: imag ignored (C2R)
            #pragma unroll
            for (int k = 1; k < Mn; k++)
                four += 2.f*(tp[k]*cww[k] - tp[Mn+k]*sww[k]);
            float v = acc + four;
            if (MODE == 1) {
                v = fmaxf(v, 0.f);
                hrow[(size_t)o*SS] = v;
                s_v[o*260 + w] = v;
            } else {
                proj += s_qw[o]*v;
            }
        }
        if (MODE == 2) {
            out[(size_t)blockIdx.x*Sn + w] = proj + qb[0];
            return;
        }
    }
    __syncthreads();

    // row DFT: thread = (o = t>>3, q0 = (t&7)*3); coalesced Y[b][y][q][c]
    int o = t >> 3, q0 = (t & 7)*3;
    const float4* xv4 = (const float4*)(s_v + o*260);
    const float4* t0p = (const float4*)(s_trig + q0*260);
    const float4* t1p = (const float4*)(s_trig + (q0+1)*260);
    const float4* t2p = (const float4*)(s_trig + (q0+2)*260);
    float a0 = 0.f, a1 = 0.f, a2 = 0.f;
    #pragma unroll 8
    for (int w4 = 0; w4 < 64; w4++) {
        float4 xv = xv4[w4];
        float4 u0 = t0p[w4], u1 = t1p[w4], u2 = t2p[w4];
        a0 += xv.x*u0.x + xv.y*u0.y + xv.z*u0.z + xv.w*u0.w;
        a1 += xv.x*u1.x + xv.y*u1.y + xv.z*u1.z + xv.w*u1.w;
        a2 += xv.x*u2.x + xv.y*u2.y + xv.z*u2.z + xv.w*u2.w;
    }
    float* yb = g_Y + (size_t)blockIdx.x*(Rn*Cn);
    float sg = (q0 >= Mn) ? -1.f : 1.f;              // Yi = -sum v*sin
    yb[(q0  )*Cn + o] = sg*a0;
    yb[(q0+1)*Cn + o] = sg*a1;
    yb[(q0+2)*Cn + o] = sg*a2;
}

#define SMEM_LAYER ((Cn*260 + Rn*260 + Cn*2*Mn + Cn*Cn + 2*Cn)*4)
#define SMEM_MODES ((256*33 + 32*25 + 33*25)*8)

extern "C" void kernel_launch(void* const* d_in, const int* in_sizes, int n_in,
                              void* d_out, int out_size) {
    (void)in_sizes; (void)n_in; (void)out_size;
    const float* x    = (const float*)d_in[0];
    const float* p_w  = (const float*)d_in[1];
    const float* p_b  = (const float*)d_in[2];
    const float* ws_w = (const float*)d_in[3];
    const float* ws_b = (const float*)d_in[4];
    const float* w1r  = (const float*)d_in[5];
    const float* w1i  = (const float*)d_in[6];
    const float* w2r  = (const float*)d_in[7];
    const float* w2i  = (const float*)d_in[8];
    const float* q_w  = (const float*)d_in[9];
    const float* q_b  = (const float*)d_in[10];
    float* out = (float*)d_out;

    cudaFuncSetAttribute(k_layer<0>, cudaFuncAttributeMaxDynamicSharedMemorySize, SMEM_LAYER);
    cudaFuncSetAttribute(k_layer<1>, cudaFuncAttributeMaxDynamicSharedMemorySize, SMEM_LAYER);
    cudaFuncSetAttribute(k_layer<2>, cudaFuncAttributeMaxDynamicSharedMemorySize, SMEM_LAYER);
    cudaFuncSetAttribute(k_modes,    cudaFuncAttributeMaxDynamicSharedMemorySize, SMEM_MODES);

    // launch indices: 0 setupA, 1 setupB, 2 k_wt, 3 layer<0>, 4 modes(0),
    // 5 layer<1>  <-- ncu -s 5 -c 1 captures this one
    k_setupA<<<Rn, Sn>>>();
    k_setupB<<<Rn, Sn>>>();
    k_wt<<<(WTN + 255)/256, 256>>>(w1r, w1i, w2r, w2i);
    k_layer<0><<<Bn*Sn, 256, SMEM_LAYER>>>(x, p_w, p_b, nullptr, nullptr, nullptr, nullptr, 0, out);
    for (int l = 0; l < Ln; l++) {
        k_modes<<<Bn*Mn, 768, SMEM_MODES>>>(l);
        if (l < Ln - 1)
            k_layer<1><<<Bn*Sn, 256, SMEM_LAYER>>>(nullptr, nullptr, nullptr,
                                                   ws_w, ws_b, q_w, q_b, l, out);
        else
            k_layer<2><<<Bn*Sn, 256, SMEM_LAYER>>>(nullptr, nullptr, nullptr,
                                                   ws_w, ws_b, q_w, q_b, l, out);
    }
}